// round 1
// baseline (speedup 1.0000x reference)
#include <cuda_runtime.h>
#include <math_constants.h>

#define D 512
#define STEPS 6
#define ATTN_BLOCKS 148
#define ATTN_THREADS 512
#define ATTN_WARPS (ATTN_THREADS / 32)

// ---- device scratch (no allocations allowed) ----
__device__ __align__(16) float g_h[2][D];
__device__ __align__(16) float g_c[2][D];
__device__ __align__(16) float g_ctx[STEPS * D];
__device__ __align__(16) float g_pm[ATTN_BLOCKS];
__device__ __align__(16) float g_pz[ATTN_BLOCKS];
__device__ __align__(16) float g_ps[ATTN_BLOCKS * D];
__device__ __align__(16) float g_y[D];

__global__ void initK() {
    int t = threadIdx.x;
    if (t < D) { g_h[0][t] = 0.f; g_c[0][t] = 0.f; }
}

// Fused  x@h  ->  online softmax  ->  sum_n w_n * x_n  (one pass over x).
// One warp per row-slice; per-lane register accumulator covers 16 dims.
__global__ __launch_bounds__(ATTN_THREADS) void attnK(const float* __restrict__ x,
                                                      int N, int hs) {
    const int tid  = threadIdx.x;
    const int wid  = tid >> 5;
    const int lane = tid & 31;

    const float4* __restrict__ x4 = (const float4*)x;
    const float4* __restrict__ h4 = (const float4*)g_h[hs];

    float4 hv[4], acc[4];
#pragma unroll
    for (int i = 0; i < 4; i++) {
        hv[i]  = h4[i * 32 + lane];
        acc[i] = make_float4(0.f, 0.f, 0.f, 0.f);
    }
    float m = -CUDART_INF_F;
    float Z = 0.f;

    const int gw = blockIdx.x * ATTN_WARPS + wid;
    const int TW = ATTN_BLOCKS * ATTN_WARPS;

    float4 xv[4];
    int r = gw;
    if (r < N) {
        const float4* row = x4 + (size_t)r * (D / 4);
#pragma unroll
        for (int i = 0; i < 4; i++) xv[i] = row[i * 32 + lane];
    }

    for (; r < N; r += TW) {
        // prefetch next row while processing current one
        float4 nx[4];
        const int rn = r + TW;
        if (rn < N) {
            const float4* row = x4 + (size_t)rn * (D / 4);
#pragma unroll
            for (int i = 0; i < 4; i++) nx[i] = row[i * 32 + lane];
        }

        float p = 0.f;
#pragma unroll
        for (int i = 0; i < 4; i++)
            p += xv[i].x * hv[i].x + xv[i].y * hv[i].y +
                 xv[i].z * hv[i].z + xv[i].w * hv[i].w;
#pragma unroll
        for (int o = 16; o; o >>= 1) p += __shfl_xor_sync(0xffffffffu, p, o);

        if (p > m) {
            const float sc = __expf(m - p);   // expf(-inf)=0 on first row
            Z = Z * sc + 1.f;
#pragma unroll
            for (int i = 0; i < 4; i++) {
                acc[i].x = acc[i].x * sc + xv[i].x;
                acc[i].y = acc[i].y * sc + xv[i].y;
                acc[i].z = acc[i].z * sc + xv[i].z;
                acc[i].w = acc[i].w * sc + xv[i].w;
            }
            m = p;
        } else {
            const float w = __expf(p - m);
            Z += w;
#pragma unroll
            for (int i = 0; i < 4; i++) {
                acc[i].x += w * xv[i].x;
                acc[i].y += w * xv[i].y;
                acc[i].z += w * xv[i].z;
                acc[i].w += w * xv[i].w;
            }
        }
#pragma unroll
        for (int i = 0; i < 4; i++) xv[i] = nx[i];
    }

    // ---- block-level online combine of 16 warp partials ----
    __shared__ float s_m[ATTN_WARPS];
    __shared__ float s_z[ATTN_WARPS];
    __shared__ __align__(16) float s_s[ATTN_WARPS * D];   // 32 KB

    if (lane == 0) { s_m[wid] = m; s_z[wid] = Z; }
    __syncthreads();

    float mb = -CUDART_INF_F;
#pragma unroll
    for (int w = 0; w < ATTN_WARPS; w++) mb = fmaxf(mb, s_m[w]);

    const float sc = __expf(m - mb);
    float4* dst = (float4*)&s_s[wid * D];
#pragma unroll
    for (int i = 0; i < 4; i++)
        dst[i * 32 + lane] = make_float4(acc[i].x * sc, acc[i].y * sc,
                                         acc[i].z * sc, acc[i].w * sc);
    __syncthreads();

    // dim-wise sum over the 16 warps (tid == dim, conflict-free)
    {
        float s = 0.f;
#pragma unroll
        for (int w = 0; w < ATTN_WARPS; w++) s += s_s[w * D + tid];
        g_ps[blockIdx.x * D + tid] = s;
    }
    if (tid == 0) {
        float zb = 0.f;
        for (int w = 0; w < ATTN_WARPS; w++) zb += s_z[w] * __expf(s_m[w] - mb);
        g_pm[blockIdx.x] = mb;
        g_pz[blockIdx.x] = zb;
    }
}

// Combine the 148 block partials into ctx[step]  (single block, coalesced).
__global__ __launch_bounds__(D) void combineK(int step) {
    const int t = threadIdx.x;
    __shared__ float buf[D];
    __shared__ float wts[ATTN_BLOCKS];

    float lm = (t < ATTN_BLOCKS) ? g_pm[t] : -CUDART_INF_F;
    buf[t] = lm;
    __syncthreads();
    for (int o = 256; o; o >>= 1) {
        if (t < o) buf[t] = fmaxf(buf[t], buf[t + o]);
        __syncthreads();
    }
    const float m = buf[0];
    __syncthreads();

    float lz = 0.f;
    if (t < ATTN_BLOCKS) {
        const float w = __expf(g_pm[t] - m);
        wts[t] = w;
        lz = w * g_pz[t];
    }
    buf[t] = lz;
    __syncthreads();
    for (int o = 256; o; o >>= 1) {
        if (t < o) buf[t] += buf[t + o];
        __syncthreads();
    }
    const float Zs = buf[0];

    float a = 0.f;
    for (int b = 0; b < ATTN_BLOCKS; b++) a += g_ps[b * D + t] * wts[b];
    g_ctx[step * D + t] = a / Zs;
}

// One block per output index j: 4 gate dot-products (len 1536) + LSTM pointwise.
// h/c double-buffered: read buffer hs, write buffer hs^1.
__global__ __launch_bounds__(128) void gatesK(const float* __restrict__ W_ih,
                                              const float* __restrict__ W_hh,
                                              const float* __restrict__ b_ih,
                                              const float* __restrict__ b_hh,
                                              int step, int hs) {
    const int j = blockIdx.x;
    const int t = threadIdx.x;
    const float* __restrict__ ctx = g_ctx + step * D;
    const float* __restrict__ h   = g_h[hs];

    const float* w0 = W_ih + (size_t)(0 * D + j) * (2 * D);
    const float* w1 = W_ih + (size_t)(1 * D + j) * (2 * D);
    const float* w2 = W_ih + (size_t)(2 * D + j) * (2 * D);
    const float* w3 = W_ih + (size_t)(3 * D + j) * (2 * D);
    const float* u0 = W_hh + (size_t)(0 * D + j) * D;
    const float* u1 = W_hh + (size_t)(1 * D + j) * D;
    const float* u2 = W_hh + (size_t)(2 * D + j) * D;
    const float* u3 = W_hh + (size_t)(3 * D + j) * D;

    float a0 = 0.f, a1 = 0.f, a2 = 0.f, a3 = 0.f;
#pragma unroll 4
    for (int col = t; col < D; col += 128) {
        const float v = ctx[col];
        a0 += w0[col] * v; a1 += w1[col] * v; a2 += w2[col] * v; a3 += w3[col] * v;
    }
#pragma unroll 4
    for (int col = t; col < D; col += 128) {
        const float v = h[col];
        a0 += w0[D + col] * v; a1 += w1[D + col] * v;
        a2 += w2[D + col] * v; a3 += w3[D + col] * v;
        a0 += u0[col] * v; a1 += u1[col] * v; a2 += u2[col] * v; a3 += u3[col] * v;
    }

    __shared__ float red[4][128];
    red[0][t] = a0; red[1][t] = a1; red[2][t] = a2; red[3][t] = a3;
    __syncthreads();
    for (int o = 64; o; o >>= 1) {
        if (t < o) {
            red[0][t] += red[0][t + o];
            red[1][t] += red[1][t + o];
            red[2][t] += red[2][t + o];
            red[3][t] += red[3][t + o];
        }
        __syncthreads();
    }
    if (t == 0) {
        float gi = red[0][0] + b_ih[0 * D + j] + b_hh[0 * D + j];
        float gf = red[1][0] + b_ih[1 * D + j] + b_hh[1 * D + j];
        float gg = red[2][0] + b_ih[2 * D + j] + b_hh[2 * D + j];
        float go = red[3][0] + b_ih[3 * D + j] + b_hh[3 * D + j];
        gi = 1.f / (1.f + __expf(-gi));
        gf = 1.f / (1.f + __expf(-gf));
        gg = tanhf(gg);
        go = 1.f / (1.f + __expf(-go));
        const float cn = gf * g_c[hs][j] + gi * gg;
        g_c[hs ^ 1][j] = cn;
        g_h[hs ^ 1][j] = go * tanhf(cn);
    }
}

__global__ __launch_bounds__(128) void projK(const float* __restrict__ Wp,
                                             const float* __restrict__ bp) {
    const int d = blockIdx.x;
    const int t = threadIdx.x;
    const float* __restrict__ wrow = Wp + (size_t)d * (STEPS * D);
    float a = 0.f;
#pragma unroll 4
    for (int k = t; k < STEPS * D; k += 128) a += wrow[k] * g_ctx[k];
    __shared__ float red[128];
    red[t] = a;
    __syncthreads();
    for (int o = 64; o; o >>= 1) {
        if (t < o) red[t] += red[t + o];
        __syncthreads();
    }
    if (t == 0) g_y[d] = red[0] + bp[d];
}

__global__ __launch_bounds__(D) void smK(float* __restrict__ out) {
    const int t = threadIdx.x;
    __shared__ float buf[D];
    const float v = g_y[t];
    buf[t] = v;
    __syncthreads();
    for (int o = 256; o; o >>= 1) {
        if (t < o) buf[t] = fmaxf(buf[t], buf[t + o]);
        __syncthreads();
    }
    const float m = buf[0];
    __syncthreads();
    const float e = __expf(v - m);
    buf[t] = e;
    __syncthreads();
    for (int o = 256; o; o >>= 1) {
        if (t < o) buf[t] += buf[t + o];
        __syncthreads();
    }
    out[t] = e / buf[0];
}

extern "C" void kernel_launch(void* const* d_in, const int* in_sizes, int n_in,
                              void* d_out, int out_size) {
    const float* x      = (const float*)d_in[0];
    const float* W_ih   = (const float*)d_in[1];
    const float* W_hh   = (const float*)d_in[2];
    const float* b_ih   = (const float*)d_in[3];
    const float* b_hh   = (const float*)d_in[4];
    const float* W_proj = (const float*)d_in[5];
    const float* b_proj = (const float*)d_in[6];
    float* out = (float*)d_out;

    const int N = in_sizes[0] / D;

    initK<<<1, D>>>();
    for (int s = 0; s < STEPS; s++) {
        const int hs = s & 1;
        attnK<<<ATTN_BLOCKS, ATTN_THREADS>>>(x, N, hs);
        combineK<<<1, D>>>(s);
        gatesK<<<D, 128>>>(W_ih, W_hh, b_ih, b_hh, s, hs);
    }
    projK<<<D, 128>>>(W_proj, b_proj);
    smK<<<1, D>>>(out);
}

// round 2
// speedup vs baseline: 1.0031x; 1.0031x over previous
#include <cuda_runtime.h>
#include <math_constants.h>

#define D 512
#define STEPS 6
#define NB 148
#define NT 512
#define NW 16
#define TW (NB * NW)

// ---- device scratch (static, zero-initialized; no allocations) ----
__device__ __align__(16) float g_ps[NB * D];
__device__ __align__(16) float g_pm[NB];
__device__ __align__(16) float g_pz[NB];
__device__ __align__(16) float g_ctx[STEPS * D];
__device__ __align__(16) float g_gates[4 * D];
__device__ __align__(16) float g_y[D];
__device__ volatile unsigned g_cnt[32];   // monotonic barrier counters

__device__ __forceinline__ float warp_sum(float v) {
#pragma unroll
    for (int o = 16; o; o >>= 1) v += __shfl_xor_sync(0xffffffffu, v, o);
    return v;
}

// Grid barrier: monotonic epoch counters -> no resets, replay-safe.
__device__ __forceinline__ void gbar(int k) {
    __syncthreads();
    if (threadIdx.x == 0) {
        __threadfence();
        unsigned prev = atomicAdd((unsigned*)(g_cnt + k), 1u);
        unsigned target = (prev / gridDim.x + 1u) * gridDim.x;
        while (g_cnt[k] < target) __nanosleep(64);
        __threadfence();
    }
    __syncthreads();
}

__global__ __launch_bounds__(NT, 1) void s2sK(const float* __restrict__ x,
                                              const float* __restrict__ W_ih,
                                              const float* __restrict__ W_hh,
                                              const float* __restrict__ b_ih,
                                              const float* __restrict__ b_hh,
                                              const float* __restrict__ W_proj,
                                              const float* __restrict__ b_proj,
                                              float* __restrict__ out,
                                              int N) {
    __shared__ __align__(16) float s_big[NW * D];    // 32 KB: warp partials / ctx stage
    __shared__ __align__(16) float s_h[D];
    __shared__ __align__(16) float s_c[D];
    __shared__ __align__(16) float s_ctx[D];
    __shared__ float s_m[NW], s_z[NW];
    __shared__ float s_w[NB];

    const int t    = threadIdx.x;
    const int wi   = t >> 5;
    const int lane = t & 31;
    const int b    = blockIdx.x;
    int bk = 0;   // barrier index

    // init h, c
    s_h[t] = 0.f;
    s_c[t] = 0.f;
    __syncthreads();

    const float4* __restrict__ x4 = (const float4*)x;

    for (int s = 0; s < STEPS; s++) {
        // ================= Phase A: fused attention pass over x =================
        {
            const float4* h4 = (const float4*)s_h;
            float4 hv[4], acc[4];
#pragma unroll
            for (int i = 0; i < 4; i++) {
                hv[i]  = h4[i * 32 + lane];
                acc[i] = make_float4(0.f, 0.f, 0.f, 0.f);
            }
            float m = -CUDART_INF_F, Z = 0.f;

            int r = b * NW + wi;
            float4 cur[4], nx1[4];
            if (r < N) {
                const float4* row = x4 + (size_t)r * (D / 4);
#pragma unroll
                for (int i = 0; i < 4; i++) cur[i] = row[i * 32 + lane];
            }
            if (r + TW < N) {
                const float4* row = x4 + (size_t)(r + TW) * (D / 4);
#pragma unroll
                for (int i = 0; i < 4; i++) nx1[i] = row[i * 32 + lane];
            }

            for (; r < N; r += TW) {
                float4 nx2[4];
                const int r2 = r + 2 * TW;
                if (r2 < N) {
                    const float4* row = x4 + (size_t)r2 * (D / 4);
#pragma unroll
                    for (int i = 0; i < 4; i++) nx2[i] = row[i * 32 + lane];
                }
                float p = 0.f;
#pragma unroll
                for (int i = 0; i < 4; i++)
                    p += cur[i].x * hv[i].x + cur[i].y * hv[i].y +
                         cur[i].z * hv[i].z + cur[i].w * hv[i].w;
                p = warp_sum(p);

                if (p > m) {
                    const float sc = __expf(m - p);
                    Z = Z * sc + 1.f;
#pragma unroll
                    for (int i = 0; i < 4; i++) {
                        acc[i].x = acc[i].x * sc + cur[i].x;
                        acc[i].y = acc[i].y * sc + cur[i].y;
                        acc[i].z = acc[i].z * sc + cur[i].z;
                        acc[i].w = acc[i].w * sc + cur[i].w;
                    }
                    m = p;
                } else {
                    const float w = __expf(p - m);
                    Z += w;
#pragma unroll
                    for (int i = 0; i < 4; i++) {
                        acc[i].x += w * cur[i].x;
                        acc[i].y += w * cur[i].y;
                        acc[i].z += w * cur[i].z;
                        acc[i].w += w * cur[i].w;
                    }
                }
#pragma unroll
                for (int i = 0; i < 4; i++) { cur[i] = nx1[i]; nx1[i] = nx2[i]; }
            }

            // block combine of 16 warp partials
            if (lane == 0) { s_m[wi] = m; s_z[wi] = Z; }
            __syncthreads();
            float mb = -CUDART_INF_F;
#pragma unroll
            for (int w = 0; w < NW; w++) mb = fmaxf(mb, s_m[w]);
            const float sc = __expf(m - mb);
            float4* dst = (float4*)&s_big[wi * D];
#pragma unroll
            for (int i = 0; i < 4; i++)
                dst[i * 32 + lane] = make_float4(acc[i].x * sc, acc[i].y * sc,
                                                 acc[i].z * sc, acc[i].w * sc);
            __syncthreads();
            {
                float ss = 0.f;
#pragma unroll
                for (int w = 0; w < NW; w++) ss += s_big[w * D + t];
                __stcg(&g_ps[b * D + t], ss);
            }
            if (t == 0) {
                float zb = 0.f;
                for (int w = 0; w < NW; w++) zb += s_z[w] * __expf(s_m[w] - mb);
                __stcg(&g_pm[b], mb);
                __stcg(&g_pz[b], zb);
            }
        }
        gbar(bk++);

        // ================= Phase B: combine partials -> ctx (blocks 0..7) =======
        if (b < 8) {
            float lm = (t < NB) ? __ldcg(&g_pm[t]) : -CUDART_INF_F;
            s_big[t] = lm;
            __syncthreads();
            for (int o = 256; o; o >>= 1) {
                if (t < o) s_big[t] = fmaxf(s_big[t], s_big[t + o]);
                __syncthreads();
            }
            const float M = s_big[0];
            __syncthreads();
            float zz = 0.f;
            if (t < NB) {
                const float w = __expf(__ldcg(&g_pm[t]) - M);
                s_w[t] = w;
                zz = w * __ldcg(&g_pz[t]);
            }
            s_big[t] = zz;
            __syncthreads();
            for (int o = 256; o; o >>= 1) {
                if (t < o) s_big[t] += s_big[t + o];
                __syncthreads();
            }
            const float Zs = s_big[0];
            __syncthreads();

            const int dim = t & 63, c = t >> 6;
            const int gd = b * 64 + dim;
            float a = 0.f;
#pragma unroll 4
            for (int q = c; q < NB; q += 8) a += __ldcg(&g_ps[q * D + gd]) * s_w[q];
            s_big[c * 64 + dim] = a;
            __syncthreads();
            if (t < 64) {
                float ssum = 0.f;
#pragma unroll
                for (int c2 = 0; c2 < 8; c2++) ssum += s_big[c2 * 64 + t];
                __stcg(&g_ctx[s * D + b * 64 + t], ssum / Zs);
            }
        }
        gbar(bk++);

        if (s == STEPS - 1) break;   // last LSTM update unused

        // ================= Phase C: gate rows (warp per row) ====================
        for (int i = t; i < D; i += NT) s_ctx[i] = __ldcg(&g_ctx[s * D + i]);
        __syncthreads();
        {
            const int row = b + NB * wi;
            if (row < 4 * D) {
                const float4* wr = (const float4*)(W_ih + (size_t)row * (2 * D));
                const float4* ur = (const float4*)(W_hh + (size_t)row * D);
                const float4* c4 = (const float4*)s_ctx;
                const float4* h4 = (const float4*)s_h;
                float a = 0.f;
#pragma unroll
                for (int i = 0; i < 4; i++) {
                    const float4 w = wr[i * 32 + lane], v = c4[i * 32 + lane];
                    a += w.x * v.x + w.y * v.y + w.z * v.z + w.w * v.w;
                }
#pragma unroll
                for (int i = 0; i < 4; i++) {
                    const float4 w = wr[(i + 4) * 32 + lane], v = h4[i * 32 + lane];
                    a += w.x * v.x + w.y * v.y + w.z * v.z + w.w * v.w;
                }
#pragma unroll
                for (int i = 0; i < 4; i++) {
                    const float4 w = ur[i * 32 + lane], v = h4[i * 32 + lane];
                    a += w.x * v.x + w.y * v.y + w.z * v.z + w.w * v.w;
                }
                a = warp_sum(a);
                if (lane == 0) __stcg(&g_gates[row], a);
            }
        }
        gbar(bk++);

        // LSTM pointwise — every block redundantly, h/c stay in local smem
        {
            const int j = t;
            float gi = __ldcg(&g_gates[j])         + b_ih[j]         + b_hh[j];
            float gf = __ldcg(&g_gates[D + j])     + b_ih[D + j]     + b_hh[D + j];
            float gg = __ldcg(&g_gates[2 * D + j]) + b_ih[2 * D + j] + b_hh[2 * D + j];
            float go = __ldcg(&g_gates[3 * D + j]) + b_ih[3 * D + j] + b_hh[3 * D + j];
            gi = 1.f / (1.f + __expf(-gi));
            gf = 1.f / (1.f + __expf(-gf));
            gg = tanhf(gg);
            go = 1.f / (1.f + __expf(-go));
            const float cn = gf * s_c[j] + gi * gg;
            s_c[j] = cn;
            s_h[j] = go * tanhf(cn);
        }
        __syncthreads();
    }

    // ================= Projection: warp per output row ==========================
    for (int i = t; i < STEPS * D; i += NT) s_big[i] = __ldcg(&g_ctx[i]);
    __syncthreads();
    {
        const int row = b + NB * wi;
        if (row < D) {
            const float4* wr = (const float4*)(W_proj + (size_t)row * (STEPS * D));
            const float4* c4 = (const float4*)s_big;
            float a = 0.f;
#pragma unroll
            for (int i = 0; i < 24; i++) {
                const float4 w = wr[i * 32 + lane], v = c4[i * 32 + lane];
                a += w.x * v.x + w.y * v.y + w.z * v.z + w.w * v.w;
            }
            a = warp_sum(a);
            if (lane == 0) __stcg(&g_y[row], a + b_proj[row]);
        }
    }
    gbar(bk++);

    // ================= Final softmax (block 0) ==================================
    if (b == 0) {
        const float v = __ldcg(&g_y[t]);
        s_big[t] = v;
        __syncthreads();
        for (int o = 256; o; o >>= 1) {
            if (t < o) s_big[t] = fmaxf(s_big[t], s_big[t + o]);
            __syncthreads();
        }
        const float M = s_big[0];
        __syncthreads();
        const float e = __expf(v - M);
        s_big[t] = e;
        __syncthreads();
        for (int o = 256; o; o >>= 1) {
            if (t < o) s_big[t] += s_big[t + o];
            __syncthreads();
        }
        out[t] = e / s_big[0];
    }
}

extern "C" void kernel_launch(void* const* d_in, const int* in_sizes, int n_in,
                              void* d_out, int out_size) {
    const float* x      = (const float*)d_in[0];
    const float* W_ih   = (const float*)d_in[1];
    const float* W_hh   = (const float*)d_in[2];
    const float* b_ih   = (const float*)d_in[3];
    const float* b_hh   = (const float*)d_in[4];
    const float* W_proj = (const float*)d_in[5];
    const float* b_proj = (const float*)d_in[6];
    float* out = (float*)d_out;
    const int N = in_sizes[0] / D;

    s2sK<<<NB, NT>>>(x, W_ih, W_hh, b_ih, b_hh, W_proj, b_proj, out, N);
}

// round 3
// speedup vs baseline: 1.3213x; 1.3172x over previous
#include <cuda_runtime.h>
#include <math_constants.h>

#define D 512
#define STEPS 6
#define NB 148
#define NT 512
#define NW 16
#define TW (NB * NW)

typedef unsigned long long u64;

// ---- device scratch (static; no allocations) ----
__device__ __align__(16) float g_ps[NB * D];
__device__ __align__(16) float g_pm[NB];
__device__ __align__(16) float g_pz[NB];
__device__ __align__(16) float g_ctx[STEPS * D];
__device__ __align__(16) float g_gates[4 * D];
__device__ __align__(16) float g_y[D];
__device__ volatile unsigned g_cnt[32];   // monotonic barrier counters

// ---- f32x2 packed helpers (sm_103a FFMA2 via PTX) ----
__device__ __forceinline__ u64 fma2(u64 a, u64 b, u64 c) {
    u64 d; asm("fma.rn.f32x2 %0, %1, %2, %3;" : "=l"(d) : "l"(a), "l"(b), "l"(c)); return d;
}
__device__ __forceinline__ u64 mul2(u64 a, u64 b) {
    u64 d; asm("mul.rn.f32x2 %0, %1, %2;" : "=l"(d) : "l"(a), "l"(b)); return d;
}
__device__ __forceinline__ u64 add2(u64 a, u64 b) {
    u64 d; asm("add.rn.f32x2 %0, %1, %2;" : "=l"(d) : "l"(a), "l"(b)); return d;
}
__device__ __forceinline__ u64 bcast2(float v) {
    u64 d; asm("mov.b64 %0, {%1, %1};" : "=l"(d) : "f"(v)); return d;
}
__device__ __forceinline__ void unpack2(u64 v, float& a, float& b) {
    asm("mov.b64 {%0, %1}, %2;" : "=f"(a), "=f"(b) : "l"(v));
}

__device__ __forceinline__ float warp_sum(float v) {
#pragma unroll
    for (int o = 16; o; o >>= 1) v += __shfl_xor_sync(0xffffffffu, v, o);
    return v;
}

// Grid barrier: monotonic epoch counters -> no resets, replay-safe.
__device__ __forceinline__ void gbar(int k) {
    __syncthreads();
    if (threadIdx.x == 0) {
        __threadfence();
        unsigned prev = atomicAdd((unsigned*)(g_cnt + k), 1u);
        unsigned target = (prev / gridDim.x + 1u) * gridDim.x;
        while (g_cnt[k] < target) __nanosleep(64);
        __threadfence();
    }
    __syncthreads();
}

// row dot against packed h (8 f32x2 per lane), two chains for ILP
__device__ __forceinline__ float dot2(const u64* v, const u64* hq) {
    u64 d0 = mul2(v[0], hq[0]);
    u64 d1 = mul2(v[1], hq[1]);
    d0 = fma2(v[2], hq[2], d0);
    d1 = fma2(v[3], hq[3], d1);
    d0 = fma2(v[4], hq[4], d0);
    d1 = fma2(v[5], hq[5], d1);
    d0 = fma2(v[6], hq[6], d0);
    d1 = fma2(v[7], hq[7], d1);
    float a, b;
    unpack2(add2(d0, d1), a, b);
    return a + b;
}

// paired warp reduction: two partials -> both full sums broadcast to all lanes
__device__ __forceinline__ void reduce2(float p0, float p1, int lane,
                                        float& s0, float& s1) {
    const bool odd = lane & 1;
    float give = odd ? p0 : p1;
    float keep = odd ? p1 : p0;
    keep += __shfl_xor_sync(0xffffffffu, give, 1);
    keep += __shfl_xor_sync(0xffffffffu, keep, 2);
    keep += __shfl_xor_sync(0xffffffffu, keep, 4);
    keep += __shfl_xor_sync(0xffffffffu, keep, 8);
    keep += __shfl_xor_sync(0xffffffffu, keep, 16);
    s0 = __shfl_sync(0xffffffffu, keep, 0);
    s1 = __shfl_sync(0xffffffffu, keep, 1);
}

__global__ __launch_bounds__(NT, 1) void s2sK(const float* __restrict__ x,
                                              const float* __restrict__ W_ih,
                                              const float* __restrict__ W_hh,
                                              const float* __restrict__ b_ih,
                                              const float* __restrict__ b_hh,
                                              const float* __restrict__ W_proj,
                                              const float* __restrict__ b_proj,
                                              float* __restrict__ out,
                                              int N) {
    __shared__ __align__(16) float s_big[NW * D];    // 32 KB
    __shared__ __align__(16) float s_h[D];
    __shared__ __align__(16) float s_c[D];
    __shared__ __align__(16) float s_ctx[D];
    __shared__ float s_m[NW], s_z[NW];
    __shared__ float s_w[NB];

    const int t    = threadIdx.x;
    const int wi   = t >> 5;
    const int lane = t & 31;
    const int b    = blockIdx.x;
    int bk = 0;

    s_h[t] = 0.f;
    s_c[t] = 0.f;
    __syncthreads();

    const ulonglong2* __restrict__ x2 = (const ulonglong2*)x;

    for (int s = 0; s < STEPS; s++) {
        // ================= Phase A: fused attention pass (one read of x) =======
        {
            const bool fwd = !(s & 1);   // serpentine: reuse L2 tail across steps
            const ulonglong2* h2 = (const ulonglong2*)s_h;
            u64 hq[8], acc[8];
#pragma unroll
            for (int i = 0; i < 4; i++) {
                ulonglong2 q = h2[i * 32 + lane];
                hq[2 * i] = q.x; hq[2 * i + 1] = q.y;
            }
#pragma unroll
            for (int i = 0; i < 8; i++) acc[i] = 0ull;
            float m = -CUDART_INF_F, Z = 0.f;

            u64 A0[8], A1[8], B0[8], B1[8];
#pragma unroll
            for (int i = 0; i < 8; i++) { A0[i] = 0; A1[i] = 0; B0[i] = 0; B1[i] = 0; }

            // load logical row rr (mapped to physical by direction)
            auto ldrow = [&](u64* v, int rr) {
                if (rr < N) {
                    const long long phys = fwd ? rr : (N - 1 - rr);
                    const ulonglong2* p = x2 + phys * 128 + lane;
#pragma unroll
                    for (int i = 0; i < 4; i++) {
                        ulonglong2 q = p[i * 32];
                        v[2 * i] = q.x; v[2 * i + 1] = q.y;
                    }
                }
            };
            // process two resident rows (logical r0, r1 = r0 + TW)
            auto step2 = [&](const u64* v0, const u64* v1, int r1) {
                float p0 = dot2(v0, hq);
                float p1 = dot2(v1, hq);
                if (r1 >= N) p1 = -CUDART_INF_F;   // warp-uniform
                float s0, s1;
                reduce2(p0, p1, lane, s0, s1);
                const float pm = fmaxf(s0, s1);
                if (pm > m) {
                    const float sc = __expf(m - pm);   // 0 on first rows
                    m = pm;
                    Z *= sc;
                    const u64 sc2 = bcast2(sc);
#pragma unroll
                    for (int i = 0; i < 8; i++) acc[i] = mul2(acc[i], sc2);
                }
                const float e0 = __expf(s0 - m);
                const float e1 = __expf(s1 - m);
                Z += e0 + e1;
                const u64 e02 = bcast2(e0);
                const u64 e12 = bcast2(e1);
#pragma unroll
                for (int i = 0; i < 8; i++) acc[i] = fma2(v0[i], e02, acc[i]);
#pragma unroll
                for (int i = 0; i < 8; i++) acc[i] = fma2(v1[i], e12, acc[i]);
            };

            int rr = b * NW + wi;
            ldrow(A0, rr); ldrow(A1, rr + TW);
            while (rr < N) {
                int rn = rr + 2 * TW;
                ldrow(B0, rn); ldrow(B1, rn + TW);
                step2(A0, A1, rr + TW);
                rr = rn;
                if (rr >= N) break;
                rn = rr + 2 * TW;
                ldrow(A0, rn); ldrow(A1, rn + TW);
                step2(B0, B1, rr + TW);
                rr = rn;
            }

            // block combine of 16 warp partials
            if (lane == 0) { s_m[wi] = m; s_z[wi] = Z; }
            __syncthreads();
            float mb = -CUDART_INF_F;
#pragma unroll
            for (int w = 0; w < NW; w++) mb = fmaxf(mb, s_m[w]);
            const float sc = __expf(m - mb);
            float4* dst = (float4*)&s_big[wi * D];
#pragma unroll
            for (int i = 0; i < 4; i++) {
                float x0, x1, x2f, x3;
                unpack2(acc[2 * i], x0, x1);
                unpack2(acc[2 * i + 1], x2f, x3);
                dst[i * 32 + lane] = make_float4(x0 * sc, x1 * sc, x2f * sc, x3 * sc);
            }
            __syncthreads();
            {
                float ss = 0.f;
#pragma unroll
                for (int w = 0; w < NW; w++) ss += s_big[w * D + t];
                __stcg(&g_ps[b * D + t], ss);
            }
            if (t == 0) {
                float zb = 0.f;
                for (int w = 0; w < NW; w++) zb += s_z[w] * __expf(s_m[w] - mb);
                __stcg(&g_pm[b], mb);
                __stcg(&g_pz[b], zb);
            }
        }
        gbar(bk++);

        // ================= Phase B: combine partials -> ctx (blocks 0..7) =======
        if (b < 8) {
            float lm = (t < NB) ? __ldcg(&g_pm[t]) : -CUDART_INF_F;
            s_big[t] = lm;
            __syncthreads();
            for (int o = 256; o; o >>= 1) {
                if (t < o) s_big[t] = fmaxf(s_big[t], s_big[t + o]);
                __syncthreads();
            }
            const float M = s_big[0];
            __syncthreads();
            float zz = 0.f;
            if (t < NB) {
                const float w = __expf(__ldcg(&g_pm[t]) - M);
                s_w[t] = w;
                zz = w * __ldcg(&g_pz[t]);
            }
            s_big[t] = zz;
            __syncthreads();
            for (int o = 256; o; o >>= 1) {
                if (t < o) s_big[t] += s_big[t + o];
                __syncthreads();
            }
            const float Zs = s_big[0];
            __syncthreads();

            const int dim = t & 63, c = t >> 6;
            const int gd = b * 64 + dim;
            float a = 0.f;
#pragma unroll 4
            for (int q = c; q < NB; q += 8) a += __ldcg(&g_ps[q * D + gd]) * s_w[q];
            s_big[c * 64 + dim] = a;
            __syncthreads();
            if (t < 64) {
                float ssum = 0.f;
#pragma unroll
                for (int c2 = 0; c2 < 8; c2++) ssum += s_big[c2 * 64 + t];
                __stcg(&g_ctx[s * D + b * 64 + t], ssum / Zs);
            }
        }
        gbar(bk++);

        if (s == STEPS - 1) break;   // last LSTM update unused

        // ================= Phase C: gate rows (warp per row) ====================
        for (int i = t; i < D; i += NT) s_ctx[i] = __ldcg(&g_ctx[s * D + i]);
        __syncthreads();
        {
            const int row = b + NB * wi;
            if (row < 4 * D) {
                const float4* wr = (const float4*)(W_ih + (size_t)row * (2 * D));
                const float4* ur = (const float4*)(W_hh + (size_t)row * D);
                const float4* c4 = (const float4*)s_ctx;
                const float4* h4 = (const float4*)s_h;
                float a = 0.f;
#pragma unroll
                for (int i = 0; i < 4; i++) {
                    const float4 w = wr[i * 32 + lane], v = c4[i * 32 + lane];
                    a += w.x * v.x + w.y * v.y + w.z * v.z + w.w * v.w;
                }
#pragma unroll
                for (int i = 0; i < 4; i++) {
                    const float4 w = wr[(i + 4) * 32 + lane], v = h4[i * 32 + lane];
                    a += w.x * v.x + w.y * v.y + w.z * v.z + w.w * v.w;
                }
#pragma unroll
                for (int i = 0; i < 4; i++) {
                    const float4 w = ur[i * 32 + lane], v = h4[i * 32 + lane];
                    a += w.x * v.x + w.y * v.y + w.z * v.z + w.w * v.w;
                }
                a = warp_sum(a);
                if (lane == 0) __stcg(&g_gates[row], a);
            }
        }
        gbar(bk++);

        // LSTM pointwise — every block redundantly, h/c stay in local smem
        {
            const int j = t;
            float gi = __ldcg(&g_gates[j])         + b_ih[j]         + b_hh[j];
            float gf = __ldcg(&g_gates[D + j])     + b_ih[D + j]     + b_hh[D + j];
            float gg = __ldcg(&g_gates[2 * D + j]) + b_ih[2 * D + j] + b_hh[2 * D + j];
            float go = __ldcg(&g_gates[3 * D + j]) + b_ih[3 * D + j] + b_hh[3 * D + j];
            gi = 1.f / (1.f + __expf(-gi));
            gf = 1.f / (1.f + __expf(-gf));
            gg = tanhf(gg);
            go = 1.f / (1.f + __expf(-go));
            const float cn = gf * s_c[j] + gi * gg;
            s_c[j] = cn;
            s_h[j] = go * tanhf(cn);
        }
        __syncthreads();
    }

    // ================= Projection: warp per output row ==========================
    for (int i = t; i < STEPS * D; i += NT) s_big[i] = __ldcg(&g_ctx[i]);
    __syncthreads();
    {
        const int row = b + NB * wi;
        if (row < D) {
            const float4* wr = (const float4*)(W_proj + (size_t)row * (STEPS * D));
            const float4* c4 = (const float4*)s_big;
            float a = 0.f;
#pragma unroll
            for (int i = 0; i < 24; i++) {
                const float4 w = wr[i * 32 + lane], v = c4[i * 32 + lane];
                a += w.x * v.x + w.y * v.y + w.z * v.z + w.w * v.w;
            }
            a = warp_sum(a);
            if (lane == 0) __stcg(&g_y[row], a + b_proj[row]);
        }
    }
    gbar(bk++);

    // ================= Final softmax (block 0) ==================================
    if (b == 0) {
        const float v = __ldcg(&g_y[t]);
        s_big[t] = v;
        __syncthreads();
        for (int o = 256; o; o >>= 1) {
            if (t < o) s_big[t] = fmaxf(s_big[t], s_big[t + o]);
            __syncthreads();
        }
        const float M = s_big[0];
        __syncthreads();
        const float e = __expf(v - M);
        s_big[t] = e;
        __syncthreads();
        for (int o = 256; o; o >>= 1) {
            if (t < o) s_big[t] += s_big[t + o];
            __syncthreads();
        }
        out[t] = e / s_big[0];
    }
}

extern "C" void kernel_launch(void* const* d_in, const int* in_sizes, int n_in,
                              void* d_out, int out_size) {
    const float* x      = (const float*)d_in[0];
    const float* W_ih   = (const float*)d_in[1];
    const float* W_hh   = (const float*)d_in[2];
    const float* b_ih   = (const float*)d_in[3];
    const float* b_hh   = (const float*)d_in[4];
    const float* W_proj = (const float*)d_in[5];
    const float* b_proj = (const float*)d_in[6];
    float* out = (float*)d_out;
    const int N = in_sizes[0] / D;

    s2sK<<<NB, NT>>>(x, W_ih, W_hh, b_ih, b_hh, W_proj, b_proj, out, N);
}